// round 3
// baseline (speedup 1.0000x reference)
#include <cuda_runtime.h>
#include <math.h>

#define C 1000          // NUM_CLASSES
#define B 1024          // BATCH
#define TPB 256
#define EPS 1e-4f
#define BETA 0.7f
#define LAMBDA1 3.0f

#define N_TGT 200000000ull              // NUM_EXAMP * NUM_CLASSES
#define COPY_BLOCKS 2048
#define TOTAL_BLOCKS (B + COPY_BLOCKS)

// ---- block reduction helpers -------------------------------------------------
__device__ __forceinline__ float block_reduce_sum(float val) {
    __shared__ float sh[8];
    __shared__ float res;
    __syncthreads();
    int lane = threadIdx.x & 31;
    int wid  = threadIdx.x >> 5;
    #pragma unroll
    for (int o = 16; o > 0; o >>= 1) val += __shfl_xor_sync(0xffffffffu, val, o);
    if (lane == 0) sh[wid] = val;
    __syncthreads();
    if (wid == 0) {
        float v = (lane < (TPB >> 5)) ? sh[lane] : 0.0f;
        #pragma unroll
        for (int o = 4; o > 0; o >>= 1) v += __shfl_xor_sync(0xffu, v, o);
        if (lane == 0) res = v;
    }
    __syncthreads();
    return res;
}

__device__ __forceinline__ float block_reduce_max(float val) {
    __shared__ float sh[8];
    __shared__ float res;
    __syncthreads();
    int lane = threadIdx.x & 31;
    int wid  = threadIdx.x >> 5;
    #pragma unroll
    for (int o = 16; o > 0; o >>= 1)
        val = fmaxf(val, __shfl_xor_sync(0xffffffffu, val, o));
    if (lane == 0) sh[wid] = val;
    __syncthreads();
    if (wid == 0) {
        float v = (lane < (TPB >> 5)) ? sh[lane] : -INFINITY;
        #pragma unroll
        for (int o = 4; o > 0; o >>= 1)
            v = fmaxf(v, __shfl_xor_sync(0xffu, v, o));
        if (lane == 0) res = v;
    }
    __syncthreads();
    return res;
}

// ---- per-row softmax/EMA/loss (blocks 0..B-1) --------------------------------
__device__ void row_work(const float* __restrict__ output,
                         const float* __restrict__ target,
                         const int*   __restrict__ label,
                         int start,
                         float*       __restrict__ out)
{
    const int r = blockIdx.x;
    const int t = threadIdx.x;
    const float* orow = output + (size_t)r * C;

    float v[4];
    #pragma unroll
    for (int i = 0; i < 4; i++) {
        int c = t + i * TPB;
        v[i] = (c < C) ? orow[c] : -INFINITY;
    }

    float m = fmaxf(fmaxf(v[0], v[1]), fmaxf(v[2], v[3]));
    m = block_reduce_max(m);

    float e[4];
    float s = 0.0f;
    #pragma unroll
    for (int i = 0; i < 4; i++) {
        int c = t + i * TPB;
        e[i] = (c < C) ? expf(v[i] - m) : 0.0f;
        s += e[i];
    }
    const float S = block_reduce_sum(s);
    const float inv_S = 1.0f / S;
    const float lse = m + logf(S);

    float yp[4];
    float cs = 0.0f;
    #pragma unroll
    for (int i = 0; i < 4; i++) {
        int c = t + i * TPB;
        if (c < C) {
            yp[i] = fminf(fmaxf(e[i] * inv_S, EPS), 1.0f - EPS);
            cs += yp[i];
        } else {
            yp[i] = 0.0f;
        }
    }
    const float inv_cs = 1.0f / block_reduce_sum(cs);

    const float* trow = target + (size_t)(start + r) * C;
    float* outrow = out + 1 + (size_t)(start + r) * C;

    float dot = 0.0f;
    #pragma unroll
    for (int i = 0; i < 4; i++) {
        int c = t + i * TPB;
        if (c < C) {
            float nt = BETA * trow[c] + (1.0f - BETA) * (yp[i] * inv_cs);
            outrow[c] = nt;
            dot += nt * yp[i];
        }
    }
    const float D = block_reduce_sum(dot);

    if (t == 0) {
        const int l = label[r];
        const float ce  = -(orow[l] - lse);
        const float elr = logf(1.0f - D);
        atomicAdd(out, (ce + LAMBDA1 * elr) * (1.0f / (float)B));
    }
}

// ---- bulk copy target -> out+1, warp-shuffle realignment ---------------------
// out chunk k   : out[4+4k .. 7+4k]   (16B aligned since out base is 256B aligned)
// needs tgt elems 3+4k .. 6+4k = { tgt4[k].w, tgt4[k+1].x, .y, .z }
__device__ void copy_work(const float* __restrict__ tgt,
                          size_t s_beg,          // EMA slice start (elem idx)
                          float* __restrict__ out)
{
    const size_t s_end = s_beg + (size_t)B * C;   // slice end (exclusive)

    // head: tgt[0..2] -> out[1..3];  tail: tgt[N_TGT-1] -> out[N_TGT]
    if (blockIdx.x == B && threadIdx.x < 4) {
        size_t j = (threadIdx.x < 3) ? (size_t)threadIdx.x : (N_TGT - 1);
        if (j < s_beg || j >= s_end) out[1 + j] = tgt[j];
    }

    const size_t NCHUNKS = (N_TGT - 4) / 4;       // 49,999,999
    const size_t NTILES  = (NCHUNKS + 31) / 32;   // warp tiles of 32 chunks

    const int    lane        = threadIdx.x & 31;
    const size_t warp_gid    = (size_t)(blockIdx.x - B) * (TPB / 32) + (threadIdx.x >> 5);
    const size_t warp_stride = (size_t)COPY_BLOCKS * (TPB / 32);

    const float4* tgt4 = reinterpret_cast<const float4*>(tgt);
    float4*       out4 = reinterpret_cast<float4*>(out + 4);   // out4[k] = out[4+4k]

    for (size_t tile = warp_gid; tile < NTILES; tile += warp_stride) {
        const size_t k0    = tile * 32;
        const size_t e_beg = 3 + 4 * k0;          // first tgt element this tile touches
        const size_t e_end = e_beg + 128;         // exclusive

        const bool full    = (k0 + 32 <= NCHUNKS);
        const bool inside  = (e_beg >= s_beg) && (e_end <= s_end);
        const bool outside = (e_end <= s_beg) || (e_beg >= s_end);

        if (full && inside) continue;             // row_work owns this region

        if (full && outside) {
            // fast path: 1 aligned LDG.128 + 3 SHFL + 1 aligned STG.128 per lane
            const size_t k = k0 + lane;
            float4 A = __ldcs(tgt4 + k);
            float4 E = A;
            if (lane == 31) E = __ldcs(tgt4 + k + 1);   // 33rd quad for the seam
            float nx = __shfl_down_sync(0xffffffffu, A.x, 1);
            float ny = __shfl_down_sync(0xffffffffu, A.y, 1);
            float nz = __shfl_down_sync(0xffffffffu, A.z, 1);
            if (lane == 31) { nx = E.x; ny = E.y; nz = E.z; }
            __stcs(out4 + k, make_float4(A.w, nx, ny, nz));
        } else {
            // rare path (<=3 tiles total): scalar per-element with slice mask
            const size_t k = k0 + lane;
            if (k < NCHUNKS) {
                const size_t j = 3 + 4 * k;
                #pragma unroll
                for (int i = 0; i < 4; i++) {
                    const size_t jj = j + i;
                    if (jj < s_beg || jj >= s_end) out[1 + jj] = tgt[jj];
                }
            }
        }
    }
}

__global__ void __launch_bounds__(TPB)
elr_fused_kernel(const float* __restrict__ output,
                 const float* __restrict__ target,
                 const int*   __restrict__ label,
                 const int*   __restrict__ index,
                 float*       __restrict__ out)
{
    const int start = (*index) * B;
    if (blockIdx.x < B) {
        row_work(output, target, label, start, out);
    } else {
        copy_work(target, (size_t)start * C, out);
    }
}

extern "C" void kernel_launch(void* const* d_in, const int* in_sizes, int n_in,
                              void* d_out, int out_size) {
    const float* output = (const float*)d_in[0];
    const float* target = (const float*)d_in[1];
    const int*   label  = (const int*)  d_in[2];
    const int*   index  = (const int*)  d_in[3];
    float* out = (float*)d_out;

    // loss accumulator slot -> 0
    cudaMemsetAsync(out, 0, sizeof(float), 0);
    // fused: per-row softmax/EMA/loss + warp-shuffle-realigned bulk copy
    elr_fused_kernel<<<TOTAL_BLOCKS, TPB, 0, 0>>>(output, target, label, index, out);
}

// round 4
// speedup vs baseline: 1.1270x; 1.1270x over previous
#include <cuda_runtime.h>
#include <math.h>

#define C 1000          // NUM_CLASSES
#define B 1024          // BATCH
#define TPB 256
#define EPS 1e-4f
#define BETA 0.7f
#define LAMBDA1 3.0f

#define N_TGT 200000000ull              // NUM_EXAMP * NUM_CLASSES
#define COPY_BLOCKS 2048
#define TOTAL_BLOCKS (B + COPY_BLOCKS)

// ---- block reduction helpers -------------------------------------------------
__device__ __forceinline__ float block_reduce_sum(float val) {
    __shared__ float sh[8];
    __shared__ float res;
    __syncthreads();
    int lane = threadIdx.x & 31;
    int wid  = threadIdx.x >> 5;
    #pragma unroll
    for (int o = 16; o > 0; o >>= 1) val += __shfl_xor_sync(0xffffffffu, val, o);
    if (lane == 0) sh[wid] = val;
    __syncthreads();
    if (wid == 0) {
        float v = (lane < (TPB >> 5)) ? sh[lane] : 0.0f;
        #pragma unroll
        for (int o = 4; o > 0; o >>= 1) v += __shfl_xor_sync(0xffu, v, o);
        if (lane == 0) res = v;
    }
    __syncthreads();
    return res;
}

__device__ __forceinline__ float block_reduce_max(float val) {
    __shared__ float sh[8];
    __shared__ float res;
    __syncthreads();
    int lane = threadIdx.x & 31;
    int wid  = threadIdx.x >> 5;
    #pragma unroll
    for (int o = 16; o > 0; o >>= 1)
        val = fmaxf(val, __shfl_xor_sync(0xffffffffu, val, o));
    if (lane == 0) sh[wid] = val;
    __syncthreads();
    if (wid == 0) {
        float v = (lane < (TPB >> 5)) ? sh[lane] : -INFINITY;
        #pragma unroll
        for (int o = 4; o > 0; o >>= 1)
            v = fmaxf(v, __shfl_xor_sync(0xffu, v, o));
        if (lane == 0) res = v;
    }
    __syncthreads();
    return res;
}

// ---- per-row softmax/EMA/loss (blocks 0..B-1) --------------------------------
__device__ void row_work(const float* __restrict__ output,
                         const float* __restrict__ target,
                         const int*   __restrict__ label,
                         int start,
                         float*       __restrict__ out)
{
    const int r = blockIdx.x;
    const int t = threadIdx.x;
    const float* orow = output + (size_t)r * C;

    float v[4];
    #pragma unroll
    for (int i = 0; i < 4; i++) {
        int c = t + i * TPB;
        v[i] = (c < C) ? orow[c] : -INFINITY;
    }

    float m = fmaxf(fmaxf(v[0], v[1]), fmaxf(v[2], v[3]));
    m = block_reduce_max(m);

    float e[4];
    float s = 0.0f;
    #pragma unroll
    for (int i = 0; i < 4; i++) {
        int c = t + i * TPB;
        e[i] = (c < C) ? expf(v[i] - m) : 0.0f;
        s += e[i];
    }
    const float S = block_reduce_sum(s);
    const float inv_S = 1.0f / S;
    const float lse = m + logf(S);

    float yp[4];
    float cs = 0.0f;
    #pragma unroll
    for (int i = 0; i < 4; i++) {
        int c = t + i * TPB;
        if (c < C) {
            yp[i] = fminf(fmaxf(e[i] * inv_S, EPS), 1.0f - EPS);
            cs += yp[i];
        } else {
            yp[i] = 0.0f;
        }
    }
    const float inv_cs = 1.0f / block_reduce_sum(cs);

    const float* trow = target + (size_t)(start + r) * C;
    float* outrow = out + 1 + (size_t)(start + r) * C;

    float dot = 0.0f;
    #pragma unroll
    for (int i = 0; i < 4; i++) {
        int c = t + i * TPB;
        if (c < C) {
            float nt = BETA * trow[c] + (1.0f - BETA) * (yp[i] * inv_cs);
            outrow[c] = nt;
            dot += nt * yp[i];
        }
    }
    const float D = block_reduce_sum(dot);

    if (t == 0) {
        const int l = label[r];
        const float ce  = -(orow[l] - lse);
        const float elr = logf(1.0f - D);
        atomicAdd(out, (ce + LAMBDA1 * elr) * (1.0f / (float)B));
    }
}

// ---- bulk copy target -> out+1 -----------------------------------------------
// Quad k: load tgt4[k] (aligned LDG.128), store 4 scalars out[1+4k..4+4k].
// Warp-iter = 128 contiguous quads (4 per lane, unrolled -> MLP=4).
// 50M quads / 128 = 390,625 groups exactly (no tail).
// EMA slice = [index*256000, +256000) quads, always 128-group aligned ->
// every group is fully inside (skip) or fully outside (copy). No masks.
__device__ void copy_work(const float* __restrict__ tgt,
                          size_t qs_beg,          // slice start, in quads
                          float* __restrict__ out)
{
    const size_t NQ      = N_TGT / 4;             // 50,000,000
    const size_t NGROUPS = NQ / 128;              // 390,625
    const size_t qs_end  = qs_beg + (size_t)(B * C) / 4;

    const int    lane    = threadIdx.x & 31;
    const size_t wg      = (size_t)(blockIdx.x - B) * (TPB / 32) + (threadIdx.x >> 5);
    const size_t wstride = (size_t)COPY_BLOCKS * (TPB / 32);

    const float4* t4 = reinterpret_cast<const float4*>(tgt);

    for (size_t g = wg; g < NGROUPS; g += wstride) {
        const size_t k0 = g * 128;
        if (k0 >= qs_beg && k0 < qs_end) continue;   // row_work owns this group

        const size_t k = k0 + lane;
        // 4 independent aligned 16B loads (hoisted -> in flight together)
        const float4 q0 = __ldcs(t4 + k);
        const float4 q1 = __ldcs(t4 + k + 32);
        const float4 q2 = __ldcs(t4 + k + 64);
        const float4 q3 = __ldcs(t4 + k + 96);

        float* o = out + 1 + 4 * k;
        __stcs(o + 0, q0.x); __stcs(o + 1, q0.y); __stcs(o + 2, q0.z); __stcs(o + 3, q0.w);
        o += 128;
        __stcs(o + 0, q1.x); __stcs(o + 1, q1.y); __stcs(o + 2, q1.z); __stcs(o + 3, q1.w);
        o += 128;
        __stcs(o + 0, q2.x); __stcs(o + 1, q2.y); __stcs(o + 2, q2.z); __stcs(o + 3, q2.w);
        o += 128;
        __stcs(o + 0, q3.x); __stcs(o + 1, q3.y); __stcs(o + 2, q3.z); __stcs(o + 3, q3.w);
    }
}

__global__ void __launch_bounds__(TPB)
elr_fused_kernel(const float* __restrict__ output,
                 const float* __restrict__ target,
                 const int*   __restrict__ label,
                 const int*   __restrict__ index,
                 float*       __restrict__ out)
{
    const int start = (*index) * B;
    if (blockIdx.x < B) {
        row_work(output, target, label, start, out);
    } else {
        copy_work(target, (size_t)start * (C / 4), out);
    }
}

extern "C" void kernel_launch(void* const* d_in, const int* in_sizes, int n_in,
                              void* d_out, int out_size) {
    const float* output = (const float*)d_in[0];
    const float* target = (const float*)d_in[1];
    const int*   label  = (const int*)  d_in[2];
    const int*   index  = (const int*)  d_in[3];
    float* out = (float*)d_out;

    // loss accumulator slot -> 0
    cudaMemsetAsync(out, 0, sizeof(float), 0);
    // fused: per-row softmax/EMA/loss + high-MLP vector-load bulk copy
    elr_fused_kernel<<<TOTAL_BLOCKS, TPB, 0, 0>>>(output, target, label, index, out);
}

// round 7
// speedup vs baseline: 1.1621x; 1.0311x over previous
#include <cuda_runtime.h>
#include <math.h>

#define C 1000          // NUM_CLASSES
#define B 1024          // BATCH
#define TPB 256
#define EPS 1e-4f
#define BETA 0.7f
#define LAMBDA1 3.0f

#define N_TGT 200000000ull              // NUM_EXAMP * NUM_CLASSES
#define GRID  912                       // 152 SMs * 6 resident blocks -> 1 wave
#define GSZ   256                       // floats per copy group (32 lanes * 8)

// ---- block reduction helpers -------------------------------------------------
__device__ __forceinline__ float block_reduce_sum(float val) {
    __shared__ float sh[8];
    __shared__ float res;
    __syncthreads();
    int lane = threadIdx.x & 31;
    int wid  = threadIdx.x >> 5;
    #pragma unroll
    for (int o = 16; o > 0; o >>= 1) val += __shfl_xor_sync(0xffffffffu, val, o);
    if (lane == 0) sh[wid] = val;
    __syncthreads();
    if (wid == 0) {
        float v = (lane < (TPB >> 5)) ? sh[lane] : 0.0f;
        #pragma unroll
        for (int o = 4; o > 0; o >>= 1) v += __shfl_xor_sync(0xffu, v, o);
        if (lane == 0) res = v;
    }
    __syncthreads();
    return res;
}

__device__ __forceinline__ float block_reduce_max(float val) {
    __shared__ float sh[8];
    __shared__ float res;
    __syncthreads();
    int lane = threadIdx.x & 31;
    int wid  = threadIdx.x >> 5;
    #pragma unroll
    for (int o = 16; o > 0; o >>= 1)
        val = fmaxf(val, __shfl_xor_sync(0xffffffffu, val, o));
    if (lane == 0) sh[wid] = val;
    __syncthreads();
    if (wid == 0) {
        float v = (lane < (TPB >> 5)) ? sh[lane] : -INFINITY;
        #pragma unroll
        for (int o = 4; o > 0; o >>= 1)
            v = fmaxf(v, __shfl_xor_sync(0xffu, v, o));
        if (lane == 0) res = v;
    }
    __syncthreads();
    return res;
}

// ---- per-row softmax/EMA/loss ------------------------------------------------
__device__ void row_work(int r,
                         const float* __restrict__ output,
                         const float* __restrict__ target,
                         const int*   __restrict__ label,
                         int start,
                         float*       __restrict__ out)
{
    const int t = threadIdx.x;
    const float* orow = output + (size_t)r * C;

    float v[4];
    #pragma unroll
    for (int i = 0; i < 4; i++) {
        int c = t + i * TPB;
        v[i] = (c < C) ? orow[c] : -INFINITY;
    }

    float m = fmaxf(fmaxf(v[0], v[1]), fmaxf(v[2], v[3]));
    m = block_reduce_max(m);

    float e[4];
    float s = 0.0f;
    #pragma unroll
    for (int i = 0; i < 4; i++) {
        int c = t + i * TPB;
        e[i] = (c < C) ? expf(v[i] - m) : 0.0f;
        s += e[i];
    }
    const float S = block_reduce_sum(s);
    const float inv_S = 1.0f / S;
    const float lse = m + logf(S);

    float yp[4];
    float cs = 0.0f;
    #pragma unroll
    for (int i = 0; i < 4; i++) {
        int c = t + i * TPB;
        if (c < C) {
            yp[i] = fminf(fmaxf(e[i] * inv_S, EPS), 1.0f - EPS);
            cs += yp[i];
        } else {
            yp[i] = 0.0f;
        }
    }
    const float inv_cs = 1.0f / block_reduce_sum(cs);

    const float* trow = target + (size_t)(start + r) * C;
    float* outrow = out + 1 + (size_t)(start + r) * C;

    float dot = 0.0f;
    #pragma unroll
    for (int i = 0; i < 4; i++) {
        int c = t + i * TPB;
        if (c < C) {
            float nt = BETA * trow[c] + (1.0f - BETA) * (yp[i] * inv_cs);
            outrow[c] = nt;
            dot += nt * yp[i];
        }
    }
    const float D = block_reduce_sum(dot);

    if (t == 0) {
        const int l = label[r];
        const float ce  = -(orow[l] - lse);
        const float elr = logf(1.0f - D);
        atomicAdd(out, (ce + LAMBDA1 * elr) * (1.0f / (float)B));
    }
}

// ---- bulk copy target -> out+1, fully warp-contiguous instructions -----------
// Group g = floats [256g, 256g+256). 2e8/256 = 781,250 groups exactly (no tail).
// Lane covers offsets lane + 32*j, j=0..7: every LDG/STG instruction spans one
// contiguous 128B line across the warp. 8 independent loads per lane (MLP=8).
// EMA slice = groups [4000*index, +4000) exactly -> branch-free group skip.
__device__ void copy_work(const float* __restrict__ tgt,
                          size_t g_beg, size_t g_end,
                          float* __restrict__ out)
{
    const size_t NGROUPS = N_TGT / GSZ;           // 781,250
    const int    lane    = threadIdx.x & 31;
    const size_t warp    = (size_t)blockIdx.x * (TPB / 32) + (threadIdx.x >> 5);
    const size_t wstride = (size_t)GRID * (TPB / 32);

    for (size_t g = warp; g < NGROUPS; g += wstride) {
        if (g >= g_beg && g < g_end) continue;    // row_work owns this group

        const float* src = tgt + g * GSZ + lane;
        float a[8];
        #pragma unroll
        for (int j = 0; j < 8; j++) a[j] = __ldcs(src + 32 * j);

        float* dst = out + 1 + g * GSZ + lane;
        #pragma unroll
        for (int j = 0; j < 8; j++) __stcs(dst + 32 * j, a[j]);
    }
}

__global__ void __launch_bounds__(TPB, 6)
elr_fused_kernel(const float* __restrict__ output,
                 const float* __restrict__ target,
                 const int*   __restrict__ label,
                 const int*   __restrict__ index,
                 float*       __restrict__ out)
{
    const int start = (*index) * B;

    // row phase: first blocks handle their row(s), rest fall through
    for (int r = blockIdx.x; r < B; r += gridDim.x)
        row_work(r, output, target, label, start, out);

    // copy phase: all blocks participate
    const size_t g_beg = (size_t)start * C / GSZ;           // = 4000 * index
    const size_t g_end = g_beg + (size_t)B * C / GSZ;       // + 4000
    copy_work(target, g_beg, g_end, out);
}

extern "C" void kernel_launch(void* const* d_in, const int* in_sizes, int n_in,
                              void* d_out, int out_size) {
    const float* output = (const float*)d_in[0];
    const float* target = (const float*)d_in[1];
    const int*   label  = (const int*)  d_in[2];
    const int*   index  = (const int*)  d_in[3];
    float* out = (float*)d_out;

    // loss accumulator slot -> 0
    cudaMemsetAsync(out, 0, sizeof(float), 0);
    // single-wave fused kernel: row softmax/EMA/loss + contiguous bulk copy
    elr_fused_kernel<<<GRID, TPB, 0, 0>>>(output, target, label, index, out);
}

// round 10
// speedup vs baseline: 1.1941x; 1.0275x over previous
#include <cuda_runtime.h>
#include <math.h>

#define C 1000          // NUM_CLASSES
#define B 1024          // BATCH
#define TPB 256
#define EPS 1e-4f
#define BETA 0.7f
#define LAMBDA1 3.0f

#define N_TGT 200000000ull              // NUM_EXAMP * NUM_CLASSES
#define GRID  912                       // 152 SMs * 6 resident blocks -> 1 wave
#define GSZ   256                       // floats per copy group (32 lanes * 8)
#define CHUNK 16                        // groups per ticket (16 KB)

__device__ unsigned long long g_ticket; // dynamic work counter (reset per launch)

// ---- block reduction helpers -------------------------------------------------
__device__ __forceinline__ float block_reduce_sum(float val) {
    __shared__ float sh[8];
    __shared__ float res;
    __syncthreads();
    int lane = threadIdx.x & 31;
    int wid  = threadIdx.x >> 5;
    #pragma unroll
    for (int o = 16; o > 0; o >>= 1) val += __shfl_xor_sync(0xffffffffu, val, o);
    if (lane == 0) sh[wid] = val;
    __syncthreads();
    if (wid == 0) {
        float v = (lane < (TPB >> 5)) ? sh[lane] : 0.0f;
        #pragma unroll
        for (int o = 4; o > 0; o >>= 1) v += __shfl_xor_sync(0xffu, v, o);
        if (lane == 0) res = v;
    }
    __syncthreads();
    return res;
}

__device__ __forceinline__ float block_reduce_max(float val) {
    __shared__ float sh[8];
    __shared__ float res;
    __syncthreads();
    int lane = threadIdx.x & 31;
    int wid  = threadIdx.x >> 5;
    #pragma unroll
    for (int o = 16; o > 0; o >>= 1)
        val = fmaxf(val, __shfl_xor_sync(0xffffffffu, val, o));
    if (lane == 0) sh[wid] = val;
    __syncthreads();
    if (wid == 0) {
        float v = (lane < (TPB >> 5)) ? sh[lane] : -INFINITY;
        #pragma unroll
        for (int o = 4; o > 0; o >>= 1)
            v = fmaxf(v, __shfl_xor_sync(0xffu, v, o));
        if (lane == 0) res = v;
    }
    __syncthreads();
    return res;
}

// ---- per-row softmax/EMA/loss ------------------------------------------------
__device__ void row_work(int r,
                         const float* __restrict__ output,
                         const float* __restrict__ target,
                         const int*   __restrict__ label,
                         int start,
                         float*       __restrict__ out)
{
    const int t = threadIdx.x;
    const float* orow = output + (size_t)r * C;

    float v[4];
    #pragma unroll
    for (int i = 0; i < 4; i++) {
        int c = t + i * TPB;
        v[i] = (c < C) ? orow[c] : -INFINITY;
    }

    float m = fmaxf(fmaxf(v[0], v[1]), fmaxf(v[2], v[3]));
    m = block_reduce_max(m);

    float e[4];
    float s = 0.0f;
    #pragma unroll
    for (int i = 0; i < 4; i++) {
        int c = t + i * TPB;
        e[i] = (c < C) ? expf(v[i] - m) : 0.0f;
        s += e[i];
    }
    const float S = block_reduce_sum(s);
    const float inv_S = 1.0f / S;
    const float lse = m + logf(S);

    float yp[4];
    float cs = 0.0f;
    #pragma unroll
    for (int i = 0; i < 4; i++) {
        int c = t + i * TPB;
        if (c < C) {
            yp[i] = fminf(fmaxf(e[i] * inv_S, EPS), 1.0f - EPS);
            cs += yp[i];
        } else {
            yp[i] = 0.0f;
        }
    }
    const float inv_cs = 1.0f / block_reduce_sum(cs);

    const float* trow = target + (size_t)(start + r) * C;
    float* outrow = out + 1 + (size_t)(start + r) * C;

    float dot = 0.0f;
    #pragma unroll
    for (int i = 0; i < 4; i++) {
        int c = t + i * TPB;
        if (c < C) {
            float nt = BETA * trow[c] + (1.0f - BETA) * (yp[i] * inv_cs);
            outrow[c] = nt;
            dot += nt * yp[i];
        }
    }
    const float D = block_reduce_sum(dot);

    if (t == 0) {
        const int l = label[r];
        const float ce  = -(orow[l] - lse);
        const float elr = logf(1.0f - D);
        atomicAdd(out, (ce + LAMBDA1 * elr) * (1.0f / (float)B));
    }
}

// ---- bulk copy target -> out+1, dynamic ticket scheduling --------------------
// Group g = floats [256g, 256g+256). 2e8/256 = 781,250 groups exactly.
// Each warp grabs CHUNK groups per ticket; warps delayed by row work or slow
// memory paths simply take fewer tickets -> finish times equalize.
// EMA slice = groups [4000*index, +4000) exactly -> group-level skip.
__device__ void copy_work(const float* __restrict__ tgt,
                          size_t g_beg, size_t g_end,
                          float* __restrict__ out)
{
    const size_t NGROUPS = N_TGT / GSZ;           // 781,250
    const int    lane    = threadIdx.x & 31;

    for (;;) {
        unsigned long long t;
        if (lane == 0) t = atomicAdd(&g_ticket, 1ULL);
        t = __shfl_sync(0xffffffffu, t, 0);
        const size_t g0 = (size_t)t * CHUNK;
        if (g0 >= NGROUPS) break;

        #pragma unroll 1
        for (int k = 0; k < CHUNK; k++) {
            const size_t g = g0 + k;
            if (g >= NGROUPS) break;
            if (g >= g_beg && g < g_end) continue;   // row_work owns this group

            const float* src = tgt + g * GSZ + lane;
            float a[8];
            #pragma unroll
            for (int j = 0; j < 8; j++) a[j] = __ldcs(src + 32 * j);

            float* dst = out + 1 + g * GSZ + lane;
            #pragma unroll
            for (int j = 0; j < 8; j++) __stcs(dst + 32 * j, a[j]);
        }
    }
}

__global__ void __launch_bounds__(TPB, 6)
elr_fused_kernel(const float* __restrict__ output,
                 const float* __restrict__ target,
                 const int*   __restrict__ label,
                 const int*   __restrict__ index,
                 float*       __restrict__ out)
{
    const int start = (*index) * B;

    // row phase: blocks with r < B handle their row(s)
    for (int r = blockIdx.x; r < B; r += gridDim.x)
        row_work(r, output, target, label, start, out);

    // copy phase: dynamically scheduled across all warps
    const size_t g_beg = (size_t)start * C / GSZ;           // = 4000 * index
    const size_t g_end = g_beg + (size_t)B * C / GSZ;       // + 4000
    copy_work(target, g_beg, g_end, out);
}

extern "C" void kernel_launch(void* const* d_in, const int* in_sizes, int n_in,
                              void* d_out, int out_size) {
    const float* output = (const float*)d_in[0];
    const float* target = (const float*)d_in[1];
    const int*   label  = (const int*)  d_in[2];
    const int*   index  = (const int*)  d_in[3];
    float* out = (float*)d_out;

    // reset dynamic work counter (graph-safe memset node, no allocation)
    void* ticket_ptr = nullptr;
    cudaGetSymbolAddress(&ticket_ptr, g_ticket);
    cudaMemsetAsync(ticket_ptr, 0, sizeof(unsigned long long), 0);

    // loss accumulator slot -> 0
    cudaMemsetAsync(out, 0, sizeof(float), 0);

    // single-wave fused kernel: row softmax/EMA/loss + ticket-scheduled copy
    elr_fused_kernel<<<GRID, TPB, 0, 0>>>(output, target, label, index, out);
}

// round 11
// speedup vs baseline: 1.2300x; 1.0301x over previous
#include <cuda_runtime.h>
#include <math.h>

#define C 1000          // NUM_CLASSES
#define B 1024          // BATCH
#define TPB 256
#define EPS 1e-4f
#define BETA 0.7f
#define LAMBDA1 3.0f

#define N_TGT 200000000ull              // NUM_EXAMP * NUM_CLASSES
#define GRID  912                       // 152 SMs * 6 resident blocks -> 1 wave
#define GSZ   256                       // out floats per copy group (32 lanes * 8)
#define CHUNK 16                        // groups per ticket (16 KB)
#define ROW_BLOCKS 256                  // blocks doing row work (4 rows each)

__device__ unsigned long long g_ticket; // dynamic work counter (reset per launch)

// ---- block reduction helpers -------------------------------------------------
__device__ __forceinline__ float block_reduce_sum(float val) {
    __shared__ float sh[8];
    __shared__ float res;
    __syncthreads();
    int lane = threadIdx.x & 31;
    int wid  = threadIdx.x >> 5;
    #pragma unroll
    for (int o = 16; o > 0; o >>= 1) val += __shfl_xor_sync(0xffffffffu, val, o);
    if (lane == 0) sh[wid] = val;
    __syncthreads();
    if (wid == 0) {
        float v = (lane < (TPB >> 5)) ? sh[lane] : 0.0f;
        #pragma unroll
        for (int o = 4; o > 0; o >>= 1) v += __shfl_xor_sync(0xffu, v, o);
        if (lane == 0) res = v;
    }
    __syncthreads();
    return res;
}

__device__ __forceinline__ float block_reduce_max(float val) {
    __shared__ float sh[8];
    __shared__ float res;
    __syncthreads();
    int lane = threadIdx.x & 31;
    int wid  = threadIdx.x >> 5;
    #pragma unroll
    for (int o = 16; o > 0; o >>= 1)
        val = fmaxf(val, __shfl_xor_sync(0xffffffffu, val, o));
    if (lane == 0) sh[wid] = val;
    __syncthreads();
    if (wid == 0) {
        float v = (lane < (TPB >> 5)) ? sh[lane] : -INFINITY;
        #pragma unroll
        for (int o = 4; o > 0; o >>= 1)
            v = fmaxf(v, __shfl_xor_sync(0xffu, v, o));
        if (lane == 0) res = v;
    }
    __syncthreads();
    return res;
}

// ---- per-row softmax/EMA/loss ------------------------------------------------
__device__ void row_work(int r,
                         const float* __restrict__ output,
                         const float* __restrict__ target,
                         const int*   __restrict__ label,
                         int start,
                         float*       __restrict__ out)
{
    const int t = threadIdx.x;
    const float* orow = output + (size_t)r * C;

    float v[4];
    #pragma unroll
    for (int i = 0; i < 4; i++) {
        int c = t + i * TPB;
        v[i] = (c < C) ? orow[c] : -INFINITY;
    }

    float m = fmaxf(fmaxf(v[0], v[1]), fmaxf(v[2], v[3]));
    m = block_reduce_max(m);

    float e[4];
    float s = 0.0f;
    #pragma unroll
    for (int i = 0; i < 4; i++) {
        int c = t + i * TPB;
        e[i] = (c < C) ? expf(v[i] - m) : 0.0f;
        s += e[i];
    }
    const float S = block_reduce_sum(s);
    const float inv_S = 1.0f / S;
    const float lse = m + logf(S);

    float yp[4];
    float cs = 0.0f;
    #pragma unroll
    for (int i = 0; i < 4; i++) {
        int c = t + i * TPB;
        if (c < C) {
            yp[i] = fminf(fmaxf(e[i] * inv_S, EPS), 1.0f - EPS);
            cs += yp[i];
        } else {
            yp[i] = 0.0f;
        }
    }
    const float inv_cs = 1.0f / block_reduce_sum(cs);

    const float* trow = target + (size_t)(start + r) * C;
    float* outrow = out + 1 + (size_t)(start + r) * C;

    float dot = 0.0f;
    #pragma unroll
    for (int i = 0; i < 4; i++) {
        int c = t + i * TPB;
        if (c < C) {
            float nt = BETA * trow[c] + (1.0f - BETA) * (yp[i] * inv_cs);
            outrow[c] = nt;
            dot += nt * yp[i];
        }
    }
    const float D = block_reduce_sum(dot);

    if (t == 0) {
        const int l = label[r];
        const float ce  = -(orow[l] - lse);
        const float elr = logf(1.0f - D);
        atomicAdd(out, (ce + LAMBDA1 * elr) * (1.0f / (float)B));
    }
}

// ---- bulk copy: out[i] = tgt[i-1] for i in [1, N_TGT], skipping EMA slice ----
// Group g owns OUT floats [256g, 256g+256): stores are 128B line-aligned with a
// single writer per line (no partial-line RMW at DRAM); loads are shifted -1
// float (overlapping read sectors become L2 hits -> no extra DRAM reads).
// Slice (out floats [s_beg, s_end)) interior groups (G0+1..G0+3999) skipped;
// the <=4 special groups (head g=0, tail, slice edges G0 / G0+4000) take a
// predicated scalar path.
__device__ void copy_work(const float* __restrict__ tgt,
                          size_t G0, size_t s_beg, size_t s_end,
                          float* __restrict__ out)
{
    const size_t NG   = N_TGT / GSZ + 1;          // 781,251 (last group = tail)
    const int    lane = threadIdx.x & 31;

    for (;;) {
        unsigned long long t;
        if (lane == 0) t = atomicAdd(&g_ticket, 1ULL);
        t = __shfl_sync(0xffffffffu, t, 0);
        const size_t gbase = (size_t)t * CHUNK;
        if (gbase >= NG) break;

        #pragma unroll 1
        for (int k = 0; k < CHUNK; k++) {
            const size_t g = gbase + k;
            if (g >= NG) break;
            if (g > G0 && g < G0 + 4000) continue;          // slice interior

            const bool partial = (g == 0) | (g + 1 == NG) |
                                 (g == G0) | (g == G0 + 4000);
            if (!partial) {
                const float* src = tgt + g * GSZ - 1 + lane;   // shifted loads
                float a[8];
                #pragma unroll
                for (int j = 0; j < 8; j++) a[j] = __ldcs(src + 32 * j);

                float* dst = out + g * GSZ + lane;             // aligned stores
                #pragma unroll
                for (int j = 0; j < 8; j++) __stcs(dst + 32 * j, a[j]);
            } else {
                #pragma unroll
                for (int j = 0; j < 8; j++) {
                    const size_t i = g * GSZ + lane + 32 * j;
                    if (i >= 1 && i <= N_TGT && (i < s_beg || i >= s_end))
                        out[i] = __ldcs(tgt + i - 1);
                }
            }
        }
    }
}

__global__ void __launch_bounds__(TPB, 6)
elr_fused_kernel(const float* __restrict__ output,
                 const float* __restrict__ target,
                 const int*   __restrict__ label,
                 const int*   __restrict__ index,
                 float*       __restrict__ out)
{
    const int start = (*index) * B;

    // row phase: only blocks 0..255 (4 rows each); rest start copying at t=0
    if (blockIdx.x < ROW_BLOCKS) {
        #pragma unroll
        for (int k = 0; k < 4; k++)
            row_work(blockIdx.x + ROW_BLOCKS * k, output, target, label, start, out);
    }

    // copy phase: ticket-scheduled across all warps
    const size_t s_beg = 1 + (size_t)start * C;          // slice in OUT indices
    const size_t s_end = s_beg + (size_t)B * C;
    const size_t G0    = (size_t)start * C / GSZ;        // = 4000 * index
    copy_work(target, G0, s_beg, s_end, out);
}

extern "C" void kernel_launch(void* const* d_in, const int* in_sizes, int n_in,
                              void* d_out, int out_size) {
    const float* output = (const float*)d_in[0];
    const float* target = (const float*)d_in[1];
    const int*   label  = (const int*)  d_in[2];
    const int*   index  = (const int*)  d_in[3];
    float* out = (float*)d_out;

    // reset dynamic work counter (graph-safe memset node, no allocation)
    void* ticket_ptr = nullptr;
    cudaGetSymbolAddress(&ticket_ptr, g_ticket);
    cudaMemsetAsync(ticket_ptr, 0, sizeof(unsigned long long), 0);

    // loss accumulator slot -> 0
    cudaMemsetAsync(out, 0, sizeof(float), 0);

    // single-wave fused kernel: dedicated row blocks + immediate-start copy
    elr_fused_kernel<<<GRID, TPB, 0, 0>>>(output, target, label, index, out);
}